// round 6
// baseline (speedup 1.0000x reference)
#include <cuda_runtime.h>
#include <cstdint>

// Problem constants
#define BATCH 16
#define CCH   512
#define HW    4096
#define NGRP  32
#define CPG   16
#define NH    8
#define HD    64
#define EPSV  1e-5f
#define ACH   8
#define CLEN  (HW / ACH)   // 512

// ---------------------------------------------------------------------------
// Scratch (device globals)
// Permuted n-layout for GEMM X operands: within each 128-n block,
//   p(n) = (n&7)*16 + ((n>>3)&15)   (inverse: n = ((p&15)<<3) | (p>>4))
// ---------------------------------------------------------------------------
__device__ float    g_qkv[(size_t)BATCH * 3 * CCH * HW];   // [b][o][n] normal
__device__ uint32_t g_ao [(size_t)BATCH * CCH * HW];       // [b][c][p] PERMUTED tf32 bits
__device__ uint32_t g_xn [(size_t)BATCH * CCH * HW];       // [b][c][p] PERMUTED tf32 bits
__device__ uint32_t g_wtq[24 * 64 * 32 * 20];              // W_qkv fragment blob
__device__ uint32_t g_wtp[ 8 * 64 * 32 * 20];              // W_proj fragment blob
__device__ float    g_sp[(size_t)BATCH * NH * ACH * HD * HD];
__device__ float    g_P [(size_t)BATCH * NH * HD * HD];

// ---------------------------------------------------------------------------
// helpers
// ---------------------------------------------------------------------------
__device__ __forceinline__ uint32_t f2t(float f) {
    uint32_t u;
    asm("cvt.rna.tf32.f32 %0, %1;" : "=r"(u) : "f"(f));
    return u;
}
__device__ __forceinline__ uint32_t sptr(const void* p) {
    uint32_t a;
    asm("{ .reg .u64 t; cvta.to.shared.u64 t, %1; cvt.u32.u64 %0, t; }" : "=r"(a) : "l"(p));
    return a;
}
__device__ __forceinline__ void cpa16(uint32_t dst, const void* src) {
    asm volatile("cp.async.cg.shared.global [%0], [%1], 16;" :: "r"(dst), "l"(src));
}
__device__ __forceinline__ void cpa_commit() { asm volatile("cp.async.commit_group;" ::: "memory"); }
__device__ __forceinline__ void cpa_wait2()  { asm volatile("cp.async.wait_group 2;" ::: "memory"); }

// ---------------------------------------------------------------------------
// Kernel 0: W -> fragment blob (unchanged from round 5)
// ---------------------------------------------------------------------------
__global__ __launch_bounds__(256) void wt_kernel(
    const float* __restrict__ Wq, const float* __restrict__ Wp)
{
    int idx = blockIdx.x * 256 + threadIdx.x;
    const float* W; uint32_t* blob; int e;
    if (idx < 49152) { W = Wq; blob = g_wtq; e = idx; }
    else             { W = Wp; blob = g_wtp; e = idx - 49152; }
    int lane = e & 31, k8 = (e >> 5) & 63, m64 = e >> 11;
    int t4 = lane & 3, g4 = lane >> 2;
    uint32_t out[16];
    #pragma unroll
    for (int w = 0; w < 16; w++) {
        int mf = w >> 2, j = w & 3;
        int kk = k8 * 8 + t4 + ((j >> 1) << 2);
        int oo = m64 * 64 + mf * 16 + g4 + ((j & 1) << 3);
        out[w] = f2t(W[(size_t)oo * CCH + kk]);
    }
    uint32_t* dst = blob + (size_t)e * 20;
    #pragma unroll
    for (int q = 0; q < 4; q++)
        *(uint4*)(dst + q * 4) = make_uint4(out[q*4], out[q*4+1], out[q*4+2], out[q*4+3]);
}

// ---------------------------------------------------------------------------
// Kernel 1: GroupNorm stats + fused normalize -> permuted tf32 g_xn
// ---------------------------------------------------------------------------
__global__ __launch_bounds__(256) void gn_kernel(
    const float* __restrict__ x,
    const float* __restrict__ gamma,
    const float* __restrict__ beta)
{
    int bg = blockIdx.x;
    int b = bg / NGRP, g = bg % NGRP;
    const float* xp = x + ((size_t)b * CCH + (size_t)g * CPG) * HW;

    int tid = threadIdx.x;
    float s = 0.f, ss = 0.f;
    const float4* xp4 = (const float4*)xp;
    const int n4 = (CPG * HW) / 4;
    for (int i = tid; i < n4; i += 256) {
        float4 v = xp4[i];
        s  += v.x + v.y + v.z + v.w;
        ss += v.x*v.x + v.y*v.y + v.z*v.z + v.w*v.w;
    }
    __shared__ float sh_s[256], sh_ss[256];
    __shared__ float sc16[CPG], bs16[CPG];
    sh_s[tid] = s; sh_ss[tid] = ss;
    __syncthreads();
    for (int off = 128; off > 0; off >>= 1) {
        if (tid < off) { sh_s[tid] += sh_s[tid+off]; sh_ss[tid] += sh_ss[tid+off]; }
        __syncthreads();
    }
    if (tid < CPG) {
        const float inv_n = 1.0f / (float)(CPG * HW);
        float mean = sh_s[0] * inv_n;
        float var  = sh_ss[0] * inv_n - mean * mean;
        float inv  = rsqrtf(var + EPSV);
        int c = g * CPG + tid;
        float ga = gamma[c], be = beta[c];
        sc16[tid] = ga * inv;
        bs16[tid] = be - mean * inv * ga;
    }
    __syncthreads();

    // normalize + permute + tf32-convert. 16 ch x 32 blk x 32 p4-quads.
    uint32_t* dstb = g_xn + ((size_t)b * CCH + (size_t)g * CPG) * HW;
    for (int i = tid; i < CPG * 1024; i += 256) {
        int ch = i >> 10, rem = i & 1023;
        int blk = rem >> 5, p4 = rem & 31;
        const float* src = xp + (size_t)ch * HW + blk * 128 + (p4 & 3) * 32 + (p4 >> 2);
        float sc = sc16[ch], bs = bs16[ch];
        uint4 u;
        u.x = f2t(fmaf(src[ 0], sc, bs));
        u.y = f2t(fmaf(src[ 8], sc, bs));
        u.z = f2t(fmaf(src[16], sc, bs));
        u.w = f2t(fmaf(src[24], sc, bs));
        *(uint4*)(dstb + (size_t)ch * HW + blk * 128 + p4 * 4) = u;
    }
}

// ---------------------------------------------------------------------------
// Kernel 2: TF32 mma.sync GEMM. 4-slot pipeline, single sync per stage.
//   C[b][o][n] = sum_k W[o][k] * X[b][k][n]  (+bias) (+res if RES)
//   X in permuted layout -> B fragments are lds.128.
// ---------------------------------------------------------------------------
#define BK    16
#define WSTG  2560               // words: 2 m64 x 2 k8 x 640
#define XSTG  (BK * 132)         // 2112 words
#define STGW  (WSTG + XSTG)      // 4672 words
#define GSMEM (4 * STGW * 4)     // 74752 bytes

template<int RES>
__global__ __launch_bounds__(256, 2) void gemm_mma(
    const uint32_t* __restrict__ Xsrc,   // [b][k][p] permuted tf32 bits
    const uint32_t* __restrict__ Wblob,
    const float* __restrict__ bias,
    const float* __restrict__ res,
    float* __restrict__ Out,
    int MO)
{
    extern __shared__ uint32_t sm[];
    const int tid = threadIdx.x, lane = tid & 31, wid = tid >> 5;
    const int b = blockIdx.z, n0 = blockIdx.x * 128, o0 = blockIdx.y * 128;
    const int m64g = o0 >> 6;
    const uint32_t* Xp = Xsrc + (size_t)b * CCH * HW;
    const uint32_t smb = sptr(sm);

    const int wm = wid >> 2, wn = wid & 3;
    const int mb = wm * 64, nb = wn * 32;
    const int g4 = lane >> 2, t4 = lane & 3;

    auto issue = [&](int s) {
        const int slot = s & 3;
        const uint32_t wd = smb + (uint32_t)slot * STGW * 4;
        const uint32_t xd = wd + WSTG * 4;
        const uint32_t* src0 = Wblob + ((size_t)m64g * 64 + 2 * s) * 640;
        const uint32_t* src1 = Wblob + ((size_t)(m64g + 1) * 64 + 2 * s) * 640;
        {
            int c = tid;
            cpa16(wd + c * 16, src0 + c * 4);
            c = tid + 256;
            cpa16(wd + c * 16, c < 320 ? src0 + c * 4 : src1 + (c - 320) * 4);
            if (tid < 128) { c = tid + 512; cpa16(wd + c * 16, src1 + (c - 320) * 4); }
        }
        {
            const int k0 = s * BK;
            int r = tid >> 5, col = tid & 31;
            cpa16(xd + (uint32_t)(r * 132 + col * 4) * 4,
                  Xp + (size_t)(k0 + r) * HW + n0 + col * 4);
            int c2 = tid + 256;
            r = c2 >> 5; col = c2 & 31;
            cpa16(xd + (uint32_t)(r * 132 + col * 4) * 4,
                  Xp + (size_t)(k0 + r) * HW + n0 + col * 4);
        }
        cpa_commit();
    };

    float acc[4][4][4];
    #pragma unroll
    for (int i = 0; i < 4; i++)
        #pragma unroll
        for (int j = 0; j < 4; j++)
            #pragma unroll
            for (int r = 0; r < 4; r++) acc[i][j][r] = 0.f;

    issue(0);
    issue(1);

    const int NS = CCH / BK;   // 32
    #pragma unroll 1
    for (int s = 0; s < NS; s++) {
        if (s + 2 < NS) issue(s + 2); else cpa_commit();
        cpa_wait2();
        __syncthreads();

        const uint32_t* ws = sm + (s & 3) * STGW;
        const uint32_t* xs = ws + WSTG;

        #pragma unroll
        for (int ks = 0; ks < 2; ks++) {
            uint4 a4[4];
            const uint32_t* wbase = ws + wm * 1280 + ks * 640 + lane * 20;
            #pragma unroll
            for (int mf = 0; mf < 4; mf++)
                a4[mf] = *(const uint4*)(wbase + mf * 4);
            // B fragments: one lds.128 per k-half covers nf=0..3
            uint4 b0 = *(const uint4*)(xs + (ks * 8 + t4    ) * 132 + g4 * 16 + wn * 4);
            uint4 b1 = *(const uint4*)(xs + (ks * 8 + t4 + 4) * 132 + g4 * 16 + wn * 4);
            uint32_t bb0[4] = { b0.x, b0.y, b0.z, b0.w };
            uint32_t bb1[4] = { b1.x, b1.y, b1.z, b1.w };
            #pragma unroll
            for (int mf = 0; mf < 4; mf++)
                #pragma unroll
                for (int nf = 0; nf < 4; nf++)
                    asm volatile(
                        "mma.sync.aligned.m16n8k8.row.col.f32.tf32.tf32.f32 "
                        "{%0,%1,%2,%3}, {%4,%5,%6,%7}, {%8,%9}, {%0,%1,%2,%3};"
                        : "+f"(acc[mf][nf][0]), "+f"(acc[mf][nf][1]),
                          "+f"(acc[mf][nf][2]), "+f"(acc[mf][nf][3])
                        : "r"(a4[mf].x), "r"(a4[mf].y), "r"(a4[mf].z), "r"(a4[mf].w),
                          "r"(bb0[nf]), "r"(bb1[nf]));
        }
    }

    // ---- epilogue (normal [b][o][n] layout) ----
    #pragma unroll
    for (int mf = 0; mf < 4; mf++) {
        int row = o0 + mb + mf * 16 + g4;
        float bv0 = bias[row], bv1 = bias[row + 8];
        #pragma unroll
        for (int nf = 0; nf < 4; nf++) {
            int col = n0 + nb + nf * 8 + t4 * 2;
            size_t a0 = ((size_t)b * MO + row)     * HW + col;
            size_t a1 = ((size_t)b * MO + row + 8) * HW + col;
            float2 v0 = { acc[mf][nf][0] + bv0, acc[mf][nf][1] + bv0 };
            float2 v1 = { acc[mf][nf][2] + bv1, acc[mf][nf][3] + bv1 };
            if (RES) {
                float2 r0 = *(const float2*)(res + a0);
                float2 r1 = *(const float2*)(res + a1);
                v0.x += r0.x; v0.y += r0.y;
                v1.x += r1.x; v1.y += r1.y;
            }
            *(float2*)(Out + a0) = v0;
            *(float2*)(Out + a1) = v1;
        }
    }
}

// ---------------------------------------------------------------------------
// Kernel 3a: QK^T partials (unchanged from round 5)
// ---------------------------------------------------------------------------
__global__ __launch_bounds__(256) void attn_qk_kernel()
{
    int blk = blockIdx.x, bh = blk >> 3, ch = blk & 7;
    int b = bh >> 3, h = bh & 7;
    const float* q = g_qkv + ((size_t)b * 3 * CCH + (size_t)h * HD) * HW;
    const float* k = g_qkv + ((size_t)b * 3 * CCH + CCH + (size_t)h * HD) * HW;

    __shared__ float qs[32][64];
    __shared__ float ks[32][64];

    int tid = threadIdx.x;
    int ty = tid >> 4, tx = tid & 15;

    float acc[4][4] = {};
    const int nbeg = ch * CLEN;
    for (int n0 = nbeg; n0 < nbeg + CLEN; n0 += 32) {
        #pragma unroll
        for (int i = 0; i < 2; i++) {
            int idx = tid + i * 256;
            int c = idx >> 3, nn4 = idx & 7;
            float4 vq = *(const float4*)(q + (size_t)c * HW + n0 + nn4 * 4);
            float4 vk = *(const float4*)(k + (size_t)c * HW + n0 + nn4 * 4);
            int col = (((c >> 2) ^ nn4) << 2) | (c & 3);
            int r = nn4 * 4;
            qs[r+0][col] = vq.x; qs[r+1][col] = vq.y; qs[r+2][col] = vq.z; qs[r+3][col] = vq.w;
            ks[r+0][col] = vk.x; ks[r+1][col] = vk.y; ks[r+2][col] = vk.z; ks[r+3][col] = vk.w;
        }
        __syncthreads();
        #pragma unroll
        for (int kk = 0; kk < 32; kk++) {
            int sw = (kk >> 2) & 7;
            float4 rq = *(const float4*)&qs[kk][(ty ^ sw) << 2];
            float4 rk = *(const float4*)&ks[kk][(tx ^ sw) << 2];
            float rqa[4] = {rq.x, rq.y, rq.z, rq.w};
            float rka[4] = {rk.x, rk.y, rk.z, rk.w};
            #pragma unroll
            for (int i = 0; i < 4; i++)
                #pragma unroll
                for (int j = 0; j < 4; j++)
                    acc[i][j] = fmaf(rqa[i], rka[j], acc[i][j]);
        }
        __syncthreads();
    }

    float* sp = g_sp + (size_t)blk * (HD * HD);
    #pragma unroll
    for (int i = 0; i < 4; i++) {
        float4 v = { acc[i][0], acc[i][1], acc[i][2], acc[i][3] };
        *(float4*)(sp + (ty * 4 + i) * HD + tx * 4) = v;
    }
}

// ---------------------------------------------------------------------------
// Kernel 3b: reduce partials + softmax (unchanged)
// ---------------------------------------------------------------------------
__global__ __launch_bounds__(64) void attn_sm_kernel()
{
    int bh = blockIdx.x;
    int r = threadIdx.x;

    float4 a[16];
    #pragma unroll
    for (int j = 0; j < 16; j++) a[j] = make_float4(0.f, 0.f, 0.f, 0.f);
    #pragma unroll
    for (int ch = 0; ch < ACH; ch++) {
        const float4* p = (const float4*)(g_sp + ((size_t)bh * ACH + ch) * (HD * HD) + r * HD);
        #pragma unroll
        for (int j = 0; j < 16; j++) {
            float4 v = p[j];
            a[j].x += v.x; a[j].y += v.y; a[j].z += v.z; a[j].w += v.w;
        }
    }
    const float scale = 0.125f;
    float mx = -1e30f;
    #pragma unroll
    for (int j = 0; j < 16; j++) {
        a[j].x *= scale; a[j].y *= scale; a[j].z *= scale; a[j].w *= scale;
        mx = fmaxf(mx, fmaxf(fmaxf(a[j].x, a[j].y), fmaxf(a[j].z, a[j].w)));
    }
    float sum = 0.f;
    #pragma unroll
    for (int j = 0; j < 16; j++) {
        a[j].x = __expf(a[j].x - mx); a[j].y = __expf(a[j].y - mx);
        a[j].z = __expf(a[j].z - mx); a[j].w = __expf(a[j].w - mx);
        sum += a[j].x + a[j].y + a[j].z + a[j].w;
    }
    float inv = 1.f / sum;
    float4* po = (float4*)(g_P + (size_t)bh * (HD * HD) + r * HD);
    #pragma unroll
    for (int j = 0; j < 16; j++) {
        a[j].x *= inv; a[j].y *= inv; a[j].z *= inv; a[j].w *= inv;
        po[j] = a[j];
    }
}

// ---------------------------------------------------------------------------
// Kernel 3c: O = P @ V; output written in PERMUTED layout (tf32 bits).
//   Column ownership per thread follows the permutation so stores are uint4.
// ---------------------------------------------------------------------------
__global__ __launch_bounds__(256) void attn_pv_kernel()
{
    int blk = blockIdx.x, bh = blk >> 3, ch = blk & 7;
    int b = bh >> 3, h = bh & 7;
    const float* v = g_qkv + ((size_t)b * 3 * CCH + 2 * CCH + (size_t)h * HD) * HW;
    uint32_t*    o = g_ao  + ((size_t)b * CCH + (size_t)h * HD) * HW;

    __shared__ float Ps[HD][68];   // Ps[d][c] = P[c][d]
    __shared__ float vs[HD][68];   // compact permuted columns q = g*8 + a*4 + j

    int tid = threadIdx.x;
    int ty = tid >> 4, tx = tid & 15;
    const int gq = tx & 7, aq = tx >> 3;   // this thread's permuted quad

    const float* P = g_P + (size_t)bh * (HD * HD);
    #pragma unroll
    for (int i = 0; i < 4; i++) {
        int idx = tid + i * 256;
        int c = idx >> 4, d4 = idx & 15;
        float4 vP = *(const float4*)(P + c * HD + d4 * 4);
        Ps[d4*4+0][c] = vP.x; Ps[d4*4+1][c] = vP.y;
        Ps[d4*4+2][c] = vP.z; Ps[d4*4+3][c] = vP.w;
    }
    __syncthreads();

    const int nbeg = ch * CLEN;
    for (int n0 = nbeg; n0 < nbeg + CLEN; n0 += 64) {
        const int h64 = (n0 >> 6) & 1;
        const int nblk = n0 >> 7;
        // load V tile, scatter into compact permuted columns:
        //   column nl (0..63) -> q = (nl&7)*8 + (nl>>3)   [a=(nl>>3)>>2, j=(nl>>3)&3 -> a*4+j = nl>>3]
        #pragma unroll
        for (int i = 0; i < 4; i++) {
            int idx = tid + i * 256;
            int d = idx >> 4, nn4 = idx & 15;
            float4 vv = *(const float4*)(v + (size_t)d * HW + n0 + nn4 * 4);
            int s8 = nn4 >> 1;                 // nl>>3 for all 4 elems
            int gb = (nn4 & 1) * 4;            // nl&7 = gb + j
            vs[d][(gb + 0) * 8 + s8] = vv.x;
            vs[d][(gb + 1) * 8 + s8] = vv.y;
            vs[d][(gb + 2) * 8 + s8] = vv.z;
            vs[d][(gb + 3) * 8 + s8] = vv.w;
        }
        __syncthreads();

        float acc[4][4] = {};
        const int qb = gq * 8 + aq * 4;
        #pragma unroll 4
        for (int d = 0; d < HD; d++) {
            float4 rp = *(const float4*)&Ps[d][ty * 4];
            float4 rv = *(const float4*)&vs[d][qb];
            float rpa[4] = {rp.x, rp.y, rp.z, rp.w};
            float rva[4] = {rv.x, rv.y, rv.z, rv.w};
            #pragma unroll
            for (int i = 0; i < 4; i++)
                #pragma unroll
                for (int j = 0; j < 4; j++)
                    acc[i][j] = fmaf(rpa[i], rva[j], acc[i][j]);
        }

        // store: permuted p = gq*16 + h64*8 + aq*4 + j  (consecutive uint4)
        const int p0 = gq * 16 + h64 * 8 + aq * 4;
        #pragma unroll
        for (int ci = 0; ci < 4; ci++) {
            int c = ty * 4 + ci;
            uint4 ov = make_uint4(f2t(acc[ci][0]), f2t(acc[ci][1]),
                                  f2t(acc[ci][2]), f2t(acc[ci][3]));
            *(uint4*)(o + (size_t)c * HW + nblk * 128 + p0) = ov;
        }
        __syncthreads();
    }
}

// ---------------------------------------------------------------------------
// Launch
// ---------------------------------------------------------------------------
extern "C" void kernel_launch(void* const* d_in, const int* in_sizes, int n_in,
                              void* d_out, int out_size)
{
    const float* x      = (const float*)d_in[0];
    const float* gamma  = (const float*)d_in[1];
    const float* beta   = (const float*)d_in[2];
    const float* w_qkv  = (const float*)d_in[3];
    const float* b_qkv  = (const float*)d_in[4];
    const float* w_proj = (const float*)d_in[5];
    const float* b_proj = (const float*)d_in[6];
    float* out = (float*)d_out;

    float *qkv_ptr;
    uint32_t *ao_ptr, *xn_ptr, *wtq_ptr, *wtp_ptr;
    cudaGetSymbolAddress((void**)&qkv_ptr, g_qkv);
    cudaGetSymbolAddress((void**)&ao_ptr,  g_ao);
    cudaGetSymbolAddress((void**)&xn_ptr,  g_xn);
    cudaGetSymbolAddress((void**)&wtq_ptr, g_wtq);
    cudaGetSymbolAddress((void**)&wtp_ptr, g_wtp);

    cudaFuncSetAttribute((const void*)gemm_mma<0>,
                         cudaFuncAttributeMaxDynamicSharedMemorySize, GSMEM);
    cudaFuncSetAttribute((const void*)gemm_mma<1>,
                         cudaFuncAttributeMaxDynamicSharedMemorySize, GSMEM);

    // 0) weight fragment blobs
    wt_kernel<<<256, 256>>>(w_qkv, w_proj);

    // 1) GroupNorm stats + fused normalize -> permuted tf32 g_xn
    gn_kernel<<<BATCH * NGRP, 256>>>(x, gamma, beta);

    // 2) qkv GEMM
    {
        dim3 grid(HW / 128, (3 * CCH) / 128, BATCH);
        gemm_mma<0><<<grid, 256, GSMEM>>>(xn_ptr, wtq_ptr, b_qkv, nullptr, qkv_ptr, 3 * CCH);
    }

    // 3) attention
    attn_qk_kernel<<<BATCH * NH * ACH, 256>>>();
    attn_sm_kernel<<<BATCH * NH, 64>>>();
    attn_pv_kernel<<<BATCH * NH * ACH, 256>>>();

    // 4) proj GEMM (residual fused)
    {
        dim3 grid(HW / 128, CCH / 128, BATCH);
        gemm_mma<1><<<grid, 256, GSMEM>>>(ao_ptr, wtp_ptr, b_proj, x, out, CCH);
    }
}